// round 8
// baseline (speedup 1.0000x reference)
#include <cuda_runtime.h>

#define IN_SZ   448
#define OUT_SZ  224
#define BATCH   64
#define PLANE   (IN_SZ * IN_SZ)

// Per-(image, output index) coefficients (mask folded in)
__device__ float2 g_a[BATCH * OUT_SZ];   // col (a0, a1)
__device__ int2   g_c[BATCH * OUT_SZ];   // col (c0, c1)
__device__ float2 g_b[BATCH * OUT_SZ];   // row (b0, b1)
__device__ int2   g_r[BATCH * OUT_SZ];   // row (r0, r1)

__device__ __forceinline__ float sig10(float z) {
    return 1.0f / (1.0f + __expf(-10.0f * z));
}

// ---------------------------------------------------------------------------
// Prologue: coefficients. grid=64, block=224. Tiny.
// ---------------------------------------------------------------------------
__global__ void racnn_coef_kernel(const float* __restrict__ locs) {
    const int b = blockIdx.x;
    const int j = threadIdx.x;            // 0..223

    float tx = locs[b * 3 + 0];
    float ty = locs[b * 3 + 1];
    float tl = locs[b * 3 + 2];

    tl = fmaxf(tl, 448.0f / 3.0f);
    tx = fminf(fmaxf(tx, tl), 448.0f - tl);
    ty = fminf(fmaxf(ty, tl), 448.0f - tl);

    const float w_off = fmaxf(floorf(tx - tl), 0.0f);
    const float h_off = fmaxf(floorf(ty - tl), 0.0f);
    const float w_end = fminf(floorf(tx + tl), 448.0f);
    const float h_end = fminf(floorf(ty + tl), 448.0f);

    const float fj = (float)j;

    // row side (w axis)
    {
        const float step = (w_end - w_off - 1.0f) * (1.0f / 223.0f);
        const float src  = w_off + fj * step;
        const float r0f  = fminf(fmaxf(floorf(src), 0.0f), 447.0f);
        const float wr   = src - r0f;
        const int   r0   = (int)r0f;
        const int   r1   = min(r0 + 1, IN_SZ - 1);
        const float mr0  = sig10(r0f - w_off) - sig10(r0f - w_end);
        const float mr1  = sig10((float)r1 - w_off) - sig10((float)r1 - w_end);
        g_b[b * OUT_SZ + j] = make_float2((1.0f - wr) * mr0, wr * mr1);
        g_r[b * OUT_SZ + j] = make_int2(r0, r1);
    }

    // column side (h axis)
    {
        const float step = (h_end - h_off - 1.0f) * (1.0f / 223.0f);
        const float src  = h_off + fj * step;
        const float c0f  = fminf(fmaxf(floorf(src), 0.0f), 447.0f);
        const float wc   = src - c0f;
        const int   c0   = (int)c0f;
        const int   c1   = min(c0 + 1, IN_SZ - 1);
        const float mc0  = sig10(c0f - h_off) - sig10(c0f - h_end);
        const float mc1  = sig10((float)c1 - h_off) - sig10((float)c1 - h_end);
        g_a[b * OUT_SZ + j] = make_float2((1.0f - wc) * mc0, wc * mc1);
        g_c[b * OUT_SZ + j] = make_int2(c0, c1);
    }
}

// ---------------------------------------------------------------------------
// Main gather: barrier-free. Thread = 1 col x 2 rows x 3 channels = 6 pixels,
// 24 independent LDGs. Block (32,8) = 256 threads covers a 32-col x 16-row
// output tile. grid (7, 14, 64) = 6272 blocks -> ~6 blocks/SM, 75% occ.
// ---------------------------------------------------------------------------
__global__ __launch_bounds__(256) void racnn_gather_kernel(
    const float* __restrict__ img, float* __restrict__ out)
{
    const int b  = blockIdx.z;
    const int jc = blockIdx.x * 32 + threadIdx.x;              // 0..223
    const int jr = blockIdx.y * 16 + threadIdx.y * 2;          // first of 2 rows

    const float2 a = __ldg(&g_a[b * OUT_SZ + jc]);
    const int2   c = __ldg(&g_c[b * OUT_SZ + jc]);

    const int2   r0 = __ldg(&g_r[b * OUT_SZ + jr]);            // warp-uniform
    const int2   r1 = __ldg(&g_r[b * OUT_SZ + jr + 1]);
    const float2 b0 = __ldg(&g_b[b * OUT_SZ + jr]);
    const float2 b1 = __ldg(&g_b[b * OUT_SZ + jr + 1]);

    const float* base = img + (size_t)b * 3 * PLANE;

    const float* p00 = base + r0.x * IN_SZ + c.x;
    const float* p01 = base + r0.x * IN_SZ + c.y;
    const float* p10 = base + r0.y * IN_SZ + c.x;
    const float* p11 = base + r0.y * IN_SZ + c.y;
    const float* q00 = base + r1.x * IN_SZ + c.x;
    const float* q01 = base + r1.x * IN_SZ + c.y;
    const float* q10 = base + r1.y * IN_SZ + c.x;
    const float* q11 = base + r1.y * IN_SZ + c.y;

    float v[3][8];
    #pragma unroll
    for (int ch = 0; ch < 3; ch++) {
        const int o = ch * PLANE;
        v[ch][0] = __ldg(p00 + o);
        v[ch][1] = __ldg(p01 + o);
        v[ch][2] = __ldg(p10 + o);
        v[ch][3] = __ldg(p11 + o);
        v[ch][4] = __ldg(q00 + o);
        v[ch][5] = __ldg(q01 + o);
        v[ch][6] = __ldg(q10 + o);
        v[ch][7] = __ldg(q11 + o);
    }

    float* obase = out + (size_t)b * 3 * OUT_SZ * OUT_SZ + jr * OUT_SZ + jc;

    #pragma unroll
    for (int ch = 0; ch < 3; ch++) {
        const float t0 = fmaf(a.y, v[ch][1], a.x * v[ch][0]);
        const float u0 = fmaf(a.y, v[ch][3], a.x * v[ch][2]);
        const float t1 = fmaf(a.y, v[ch][5], a.x * v[ch][4]);
        const float u1 = fmaf(a.y, v[ch][7], a.x * v[ch][6]);
        float* op = obase + (size_t)ch * OUT_SZ * OUT_SZ;
        op[0]      = fmaf(b0.y, u0, b0.x * t0);
        op[OUT_SZ] = fmaf(b1.y, u1, b1.x * t1);
    }
}

// ---------------------------------------------------------------------------
extern "C" void kernel_launch(void* const* d_in, const int* in_sizes, int n_in,
                              void* d_out, int out_size)
{
    const float* images = (const float*)d_in[0];
    const float* locs   = (const float*)d_in[1];
    if (n_in >= 2 && in_sizes[0] == BATCH * 3) {
        locs   = (const float*)d_in[0];
        images = (const float*)d_in[1];
    }
    float* out = (float*)d_out;

    racnn_coef_kernel<<<BATCH, OUT_SZ>>>(locs);

    dim3 block(32, 8, 1);                 // 256 threads
    dim3 grid(7, 14, BATCH);              // (7, 14, 64) = 6272 blocks
    racnn_gather_kernel<<<grid, block>>>(images, out);
}